// round 3
// baseline (speedup 1.0000x reference)
#include <cuda_runtime.h>
#include <math.h>

#define TOKENS 8192
#define DDIM   1024
#define NEXP   8

#define BM 128
#define BN 128
#define BK 16

// Scratch (allocation-free rule: __device__ globals)
__device__ int   g_cnt[NEXP];
__device__ int   g_tok[NEXP][TOKENS];
__device__ float g_wt [NEXP][TOKENS];

__global__ void zero_cnt_kernel() {
    if (threadIdx.x < NEXP) g_cnt[threadIdx.x] = 0;
}

// One warp per token: gate scores, top-2, softmax over the two, bucket append.
__global__ void gate_kernel(const float* __restrict__ x,
                            const float* __restrict__ Wg,
                            const float* __restrict__ bg) {
    int warp = threadIdx.x >> 5;
    int lane = threadIdx.x & 31;
    int t = blockIdx.x * 8 + warp;        // grid = TOKENS/8 blocks of 256
    const float* xr = x + (size_t)t * DDIM;

    float acc[NEXP];
#pragma unroll
    for (int e = 0; e < NEXP; e++) acc[e] = 0.f;

    for (int d = lane; d < DDIM; d += 32) {
        float xv = xr[d];
        const float4* wr = reinterpret_cast<const float4*>(Wg + (size_t)d * NEXP);
        float4 w0 = wr[0];
        float4 w1 = wr[1];
        acc[0] += xv * w0.x; acc[1] += xv * w0.y;
        acc[2] += xv * w0.z; acc[3] += xv * w0.w;
        acc[4] += xv * w1.x; acc[5] += xv * w1.y;
        acc[6] += xv * w1.z; acc[7] += xv * w1.w;
    }
#pragma unroll
    for (int e = 0; e < NEXP; e++) {
#pragma unroll
        for (int o = 16; o > 0; o >>= 1)
            acc[e] += __shfl_down_sync(0xffffffffu, acc[e], o);
    }

    if (lane == 0) {
        float v1 = -INFINITY, v2 = -INFINITY;
        int   i1 = 0, i2 = 0;
#pragma unroll
        for (int e = 0; e < NEXP; e++) {
            float v = acc[e] + bg[e];
            if (v > v1)      { v2 = v1; i2 = i1; v1 = v; i1 = e; }
            else if (v > v2) { v2 = v;  i2 = e; }
        }
        // softmax over {v1, v2} (others are exp(-inf)=0)
        float l     = __expf(v2 - v1);
        float denom = 1.f + l;
        float w1v   = 1.f / denom;
        float w2v   = l / denom;

        int p1 = atomicAdd(&g_cnt[i1], 1);
        g_tok[i1][p1] = t; g_wt[i1][p1] = w1v;
        int p2 = atomicAdd(&g_cnt[i2], 1);
        g_tok[i2][p2] = t; g_wt[i2][p2] = w2v;
    }
}

// Grouped GEMM: per expert, gathered-row X tile @ We[e], scaled by gate weight,
// scatter-accumulated into out with fp32 atomics (exactly 2 adds per element ->
// commutative -> deterministic). Packed fma.rn.f32x2 accumulators (2 FMA/inst).
__global__ __launch_bounds__(256, 2)
void moe_gemm_kernel(const float* __restrict__ x,
                     const float* __restrict__ We,
                     const float* __restrict__ be,
                     float* __restrict__ out) {
    const int e    = blockIdx.z;
    const int n    = g_cnt[e];
    const int row0 = blockIdx.y * BM;
    if (row0 >= n) return;
    const int col0   = blockIdx.x * BN;
    const int nvalid = min(BM, n - row0);

    __shared__ float As[BK][BM];
    __shared__ float Bs[BK][BN];
    __shared__ int   tok_s[BM];
    __shared__ float w_s[BM];

    const int tid = threadIdx.x;
    if (tid < BM) {
        if (tid < nvalid) {
            tok_s[tid] = g_tok[e][row0 + tid];
            w_s[tid]   = g_wt[e][row0 + tid];
        } else {
            tok_s[tid] = 0;
            w_s[tid]   = 0.f;
        }
    }
    __syncthreads();

    const float* B = We + (size_t)e * DDIM * DDIM + col0;  // [d][h], col-shifted

    const int ty = tid >> 4;   // 0..15 -> rows ty*8..ty*8+7
    const int tx = tid & 15;   // 0..15 -> cols tx*8..tx*8+7

    // A loader: float4 id f=tid -> row f>>2, k-sub (f&3)*4; second f=tid+256
    const int a_row0 = tid >> 2;
    const int a_kk   = (tid & 3) * 4;
    const int a_row1 = a_row0 + 64;
    // B loader: float4 id f=tid -> brow f>>5, col (f&31)*4; second f=tid+256
    const int b_row0 = tid >> 5;
    const int b_col  = (tid & 31) * 4;
    const int b_row1 = b_row0 + 8;

    const float* xA0 = x + (size_t)tok_s[a_row0] * DDIM + a_kk;
    const float* xA1 = x + (size_t)tok_s[a_row1] * DDIM + a_kk;

    unsigned long long acc[8][4];
#pragma unroll
    for (int i = 0; i < 8; i++)
#pragma unroll
        for (int j = 0; j < 4; j++) acc[i][j] = 0ull;

    for (int kt = 0; kt < DDIM; kt += BK) {
        float4 va0 = *reinterpret_cast<const float4*>(xA0 + kt);
        float4 va1 = *reinterpret_cast<const float4*>(xA1 + kt);
        float4 vb0 = *reinterpret_cast<const float4*>(B + (size_t)(kt + b_row0) * DDIM + b_col);
        float4 vb1 = *reinterpret_cast<const float4*>(B + (size_t)(kt + b_row1) * DDIM + b_col);

        __syncthreads();   // previous iteration's reads done
        As[a_kk + 0][a_row0] = va0.x;
        As[a_kk + 1][a_row0] = va0.y;
        As[a_kk + 2][a_row0] = va0.z;
        As[a_kk + 3][a_row0] = va0.w;
        As[a_kk + 0][a_row1] = va1.x;
        As[a_kk + 1][a_row1] = va1.y;
        As[a_kk + 2][a_row1] = va1.z;
        As[a_kk + 3][a_row1] = va1.w;
        *reinterpret_cast<float4*>(&Bs[b_row0][b_col]) = vb0;
        *reinterpret_cast<float4*>(&Bs[b_row1][b_col]) = vb1;
        __syncthreads();

#pragma unroll
        for (int k = 0; k < BK; ++k) {
            uint4 a0 = *reinterpret_cast<const uint4*>(&As[k][ty * 8]);
            uint4 a1 = *reinterpret_cast<const uint4*>(&As[k][ty * 8 + 4]);
            ulonglong2 bA = *reinterpret_cast<const ulonglong2*>(&Bs[k][tx * 8]);
            ulonglong2 bB = *reinterpret_cast<const ulonglong2*>(&Bs[k][tx * 8 + 4]);
            unsigned int av[8] = {a0.x, a0.y, a0.z, a0.w, a1.x, a1.y, a1.z, a1.w};
            unsigned long long bp[4] = {bA.x, bA.y, bB.x, bB.y};
#pragma unroll
            for (int i = 0; i < 8; ++i) {
                unsigned long long a2;
                asm("mov.b64 %0, {%1, %1};" : "=l"(a2) : "r"(av[i]));
#pragma unroll
                for (int j = 0; j < 4; ++j) {
                    asm("fma.rn.f32x2 %0, %1, %2, %0;"
                        : "+l"(acc[i][j])
                        : "l"(a2), "l"(bp[j]));
                }
            }
        }
    }

    // Epilogue: out[tok, col] += w * (acc + be[e, col])
#pragma unroll
    for (int i = 0; i < 8; ++i) {
        const int r = ty * 8 + i;
        if (r < nvalid) {
            const int   tok = tok_s[r];
            const float w   = w_s[r];
            float*       orow  = out + (size_t)tok * DDIM + col0 + tx * 8;
            const float* berow = be + (size_t)e * DDIM + col0 + tx * 8;
#pragma unroll
            for (int j = 0; j < 4; ++j) {
                float lo = __uint_as_float((unsigned)(acc[i][j] & 0xffffffffull));
                float hi = __uint_as_float((unsigned)(acc[i][j] >> 32));
                atomicAdd(&orow[j * 2 + 0], w * (lo + berow[j * 2 + 0]));
                atomicAdd(&orow[j * 2 + 1], w * (hi + berow[j * 2 + 1]));
            }
        }
    }
}

extern "C" void kernel_launch(void* const* d_in, const int* in_sizes, int n_in,
                              void* d_out, int out_size) {
    const float* x  = (const float*)d_in[0];
    const float* Wg = (const float*)d_in[1];
    const float* bg = (const float*)d_in[2];
    const float* We = (const float*)d_in[3];
    const float* be = (const float*)d_in[4];
    float* out = (float*)d_out;

    zero_cnt_kernel<<<1, 32>>>();
    gate_kernel<<<TOKENS / 8, 256>>>(x, Wg, bg);
    cudaMemsetAsync(out, 0, (size_t)out_size * sizeof(float));

    dim3 grid(DDIM / BN, TOKENS / BM, NEXP);   // (8, 64, 8); empty row-tiles early-exit
    moe_gemm_kernel<<<grid, 256>>>(x, We, be, out);
}

// round 5
// speedup vs baseline: 1.9579x; 1.9579x over previous
#include <cuda_runtime.h>
#include <cuda_bf16.h>
#include <stdint.h>
#include <math.h>

#define TOKENS 8192
#define DDIM   1024
#define NEXP   8

#define BM 128
#define BN 128
#define BK 32
#define NKT (DDIM / BK)   // 32 k-chunks

// ---------------- scratch (allocation-free rule: __device__ globals) ----------------
__device__ int   g_cnt[NEXP];
__device__ int   g_tok[NEXP][TOKENS];
__device__ float g_wt [NEXP][TOKENS];

// ---------------- helpers ----------------
__device__ __forceinline__ uint32_t smem_u32(const void* p) {
    uint32_t a;
    asm("{ .reg .u64 t; cvta.to.shared.u64 t, %1; cvt.u32.u64 %0, t; }" : "=r"(a) : "l"(p));
    return a;
}

// XOR swizzle within an 8KB tile of 128 rows x 64B: makes ldmatrix (8 rows,
// 16B each, row stride 64B) conflict-free. slot(bits 4-5) ^= rowpair(bits 7-8).
#define SWZ(o) ((o) ^ ((((o) >> 7) & 3) << 4))

// fp32 pair (va=k, vb=k+1) -> bf16x2 hi and residual-lo bf16x2
__device__ __forceinline__ void cvt_pair_hl(float va, float vb, uint32_t& hi, uint32_t& lo) {
    float ha = __bfloat162float(__float2bfloat16(va));
    float hb = __bfloat162float(__float2bfloat16(vb));
    asm("cvt.rn.bf16x2.f32 %0, %1, %2;" : "=r"(hi) : "f"(hb), "f"(ha));
    float la = va - ha, lb = vb - hb;
    asm("cvt.rn.bf16x2.f32 %0, %1, %2;" : "=r"(lo) : "f"(lb), "f"(la));
}

__device__ __forceinline__ void ldsm_x4(uint32_t* r, uint32_t addr) {
    asm volatile("ldmatrix.sync.aligned.m8n8.x4.shared.b16 {%0,%1,%2,%3}, [%4];"
                 : "=r"(r[0]), "=r"(r[1]), "=r"(r[2]), "=r"(r[3]) : "r"(addr));
}

__device__ __forceinline__ void mma_bf16(float* c, const uint32_t* a, uint32_t b0, uint32_t b1) {
    asm volatile("mma.sync.aligned.m16n8k16.row.col.f32.bf16.bf16.f32 "
                 "{%0,%1,%2,%3}, {%4,%5,%6,%7}, {%8,%9}, {%0,%1,%2,%3};"
                 : "+f"(c[0]), "+f"(c[1]), "+f"(c[2]), "+f"(c[3])
                 : "r"(a[0]), "r"(a[1]), "r"(a[2]), "r"(a[3]), "r"(b0), "r"(b1));
}

// ---------------- SMEM layout (dynamic) ----------------
// [0]    tok_s (128*4)
// [512]  w_s   (128*4)
// [1024] stage0: Ah 8K | Al 8K | Bh 8K | Bl 8K   (32KB)
// [33792] stage1: same
#define SM_TOK   0
#define SM_W     512
#define SM_TILE  1024
#define STAGE_BYTES 32768
#define SMEM_TOTAL (SM_TILE + 2 * STAGE_BYTES)   // 66560

// ---------------- small kernels ----------------
__global__ void zero_cnt_kernel() {
    if (threadIdx.x < NEXP) g_cnt[threadIdx.x] = 0;
}

__global__ void gate_kernel(const float* __restrict__ x,
                            const float* __restrict__ Wg,
                            const float* __restrict__ bg) {
    int warp = threadIdx.x >> 5;
    int lane = threadIdx.x & 31;
    int t = blockIdx.x * 8 + warp;
    const float* xr = x + (size_t)t * DDIM;

    float acc[NEXP];
#pragma unroll
    for (int e = 0; e < NEXP; e++) acc[e] = 0.f;

    for (int d = lane; d < DDIM; d += 32) {
        float xv = xr[d];
        const float4* wr = reinterpret_cast<const float4*>(Wg + (size_t)d * NEXP);
        float4 w0 = wr[0];
        float4 w1 = wr[1];
        acc[0] += xv * w0.x; acc[1] += xv * w0.y;
        acc[2] += xv * w0.z; acc[3] += xv * w0.w;
        acc[4] += xv * w1.x; acc[5] += xv * w1.y;
        acc[6] += xv * w1.z; acc[7] += xv * w1.w;
    }
#pragma unroll
    for (int e = 0; e < NEXP; e++) {
#pragma unroll
        for (int o = 16; o > 0; o >>= 1)
            acc[e] += __shfl_down_sync(0xffffffffu, acc[e], o);
    }

    if (lane == 0) {
        float v1 = -INFINITY, v2 = -INFINITY;
        int   i1 = 0, i2 = 0;
#pragma unroll
        for (int e = 0; e < NEXP; e++) {
            float v = acc[e] + bg[e];
            if (v > v1)      { v2 = v1; i2 = i1; v1 = v; i1 = e; }
            else if (v > v2) { v2 = v;  i2 = e; }
        }
        float l     = __expf(v2 - v1);
        float denom = 1.f + l;
        float w1v   = 1.f / denom;
        float w2v   = l / denom;

        int p1 = atomicAdd(&g_cnt[i1], 1);
        g_tok[i1][p1] = t; g_wt[i1][p1] = w1v;
        int p2 = atomicAdd(&g_cnt[i2], 1);
        g_tok[i2][p2] = t; g_wt[i2][p2] = w2v;
    }
}

// ---------------- HMMA grouped GEMM ----------------
// D[128,128] = gathered_x[128,1024] @ We[e][1024, col0:col0+128]
// bf16 2-term split, 3 passes: Ah*Bh + Ah*Bl + Al*Bh, fp32 mma accum.
__global__ __launch_bounds__(256, 1)
void moe_gemm_mma(const float* __restrict__ x,
                  const float* __restrict__ We,
                  const float* __restrict__ be,
                  float* __restrict__ out) {
    const int e    = blockIdx.z;
    const int n    = g_cnt[e];
    const int row0 = blockIdx.x * BM;
    if (row0 >= n) return;
    const int col0   = blockIdx.y * BN;
    const int nvalid = min(BM, n - row0);

    extern __shared__ char smem[];
    int*   tok_s = (int*)(smem + SM_TOK);
    float* w_s   = (float*)(smem + SM_W);
    char*  tiles = smem + SM_TILE;
    const uint32_t tiles_u = smem_u32(tiles);

    const int tid  = threadIdx.x;
    const int lane = tid & 31;
    const int wid  = tid >> 5;

    if (tid < BM) {
        int tk = 0; float w = 0.f;
        if (tid < nvalid) { tk = g_tok[e][row0 + tid]; w = g_wt[e][row0 + tid]; }
        tok_s[tid] = tk;
        w_s[tid]   = w;
    }
    __syncthreads();

    // ---- staging assignment ----
    // A: 2 threads/row, each 16 consecutive k (4 float4)
    const int a_row = tid >> 1;
    const int a_k0  = (tid & 1) * 16;
    const float* a_src = x + (size_t)tok_s[a_row] * DDIM + a_k0;
    // B: thread covers 4 n at 4 consecutive k rows (kb = (tid>>5)*4)
    const int b_n0 = (tid & 31) * 4;
    const int b_kb = (tid >> 5) * 4;
    const float* b_src = We + (size_t)e * DDIM * DDIM + col0 + b_n0;

    // ---- compute assignment: warp tile 64x32 ----
    const int m0  = (wid & 1) * 64;
    const int n0w = (wid >> 1) * 32;
    // ldmatrix lane-local terms
    const int a_lrow = (lane & 7) + ((lane >> 3) & 1) * 8;  // row within 16
    const int a_lk   = ((lane >> 4) & 1) * 8;               // k block
    const int b_lrow = (lane & 7) + ((lane >> 4) & 1) * 8;  // n within 16
    const int b_lk   = ((lane >> 3) & 1) * 8;               // k block

    float acc[4][4][4];
#pragma unroll
    for (int i = 0; i < 4; i++)
#pragma unroll
        for (int j = 0; j < 4; j++)
#pragma unroll
            for (int q = 0; q < 4; q++) acc[i][j][q] = 0.f;

    float4 av[4], bv[4];

    // prefetch chunk 0
#pragma unroll
    for (int q = 0; q < 4; q++) av[q] = *reinterpret_cast<const float4*>(a_src + q * 4);
#pragma unroll
    for (int i = 0; i < 4; i++)
        bv[i] = *reinterpret_cast<const float4*>(b_src + (size_t)(b_kb + i) * DDIM);

    // stage chunk 0 -> buffer 0
    {
        char* Ah = tiles;           char* Al = tiles + 8192;
        char* Bh = tiles + 16384;   char* Bl = tiles + 24576;
#pragma unroll
        for (int q = 0; q < 4; q++) {
            uint32_t h01, l01, h23, l23;
            cvt_pair_hl(av[q].x, av[q].y, h01, l01);
            cvt_pair_hl(av[q].z, av[q].w, h23, l23);
            const uint32_t o = SWZ((uint32_t)(a_row * 64 + a_k0 * 2 + q * 8));
            *reinterpret_cast<uint2*>(Ah + o) = make_uint2(h01, h23);
            *reinterpret_cast<uint2*>(Al + o) = make_uint2(l01, l23);
        }
        float b0[4] = {bv[0].x, bv[0].y, bv[0].z, bv[0].w};
        float b1[4] = {bv[1].x, bv[1].y, bv[1].z, bv[1].w};
        float b2[4] = {bv[2].x, bv[2].y, bv[2].z, bv[2].w};
        float b3[4] = {bv[3].x, bv[3].y, bv[3].z, bv[3].w};
#pragma unroll
        for (int j = 0; j < 4; j++) {
            uint32_t h01, l01, h23, l23;
            cvt_pair_hl(b0[j], b1[j], h01, l01);
            cvt_pair_hl(b2[j], b3[j], h23, l23);
            const uint32_t o = SWZ((uint32_t)((b_n0 + j) * 64 + b_kb * 2));
            *reinterpret_cast<uint2*>(Bh + o) = make_uint2(h01, h23);
            *reinterpret_cast<uint2*>(Bl + o) = make_uint2(l01, l23);
        }
    }
    __syncthreads();

    for (int kt = 0; kt < NKT; kt++) {
        const int cur = kt & 1;

        // prefetch next chunk's globals into registers (hidden under mma)
        if (kt + 1 < NKT) {
            const int kk = (kt + 1) * BK;
#pragma unroll
            for (int q = 0; q < 4; q++)
                av[q] = *reinterpret_cast<const float4*>(a_src + kk + q * 4);
#pragma unroll
            for (int i = 0; i < 4; i++)
                bv[i] = *reinterpret_cast<const float4*>(b_src + (size_t)(kk + b_kb + i) * DDIM);
        }

        // ---- compute on buffer cur ----
        const uint32_t AhU = tiles_u + cur * STAGE_BYTES;
        const uint32_t BhU = AhU + 16384;
#pragma unroll
        for (int ks = 0; ks < 2; ks++) {
            uint32_t ah[4][4], al[4][4], bh[2][4], bl[2][4];
#pragma unroll
            for (int mt = 0; mt < 4; mt++) {
                const uint32_t o = SWZ((uint32_t)((m0 + mt * 16 + a_lrow) * 64 +
                                                  (ks * 16 + a_lk) * 2));
                ldsm_x4(ah[mt], AhU + o);
                ldsm_x4(al[mt], AhU + 8192 + o);
            }
#pragma unroll
            for (int bp = 0; bp < 2; bp++) {
                const uint32_t o = SWZ((uint32_t)((n0w + bp * 16 + b_lrow) * 64 +
                                                  (ks * 16 + b_lk) * 2));
                ldsm_x4(bh[bp], BhU + o);
                ldsm_x4(bl[bp], BhU + 8192 + o);
            }
            // pass 0: Ah*Bh ; pass 1: Ah*Bl ; pass 2: Al*Bh
#pragma unroll
            for (int mt = 0; mt < 4; mt++)
#pragma unroll
                for (int nt = 0; nt < 4; nt++) {
                    const int bp = nt >> 1, bo = (nt & 1) * 2;
                    mma_bf16(acc[mt][nt], ah[mt], bh[bp][bo], bh[bp][bo + 1]);
                    mma_bf16(acc[mt][nt], ah[mt], bl[bp][bo], bl[bp][bo + 1]);
                    mma_bf16(acc[mt][nt], al[mt], bh[bp][bo], bh[bp][bo + 1]);
                }
        }

        // ---- stage next chunk into the other buffer ----
        if (kt + 1 < NKT) {
            char* Ah = tiles + ((kt + 1) & 1) * STAGE_BYTES;
            char* Al = Ah + 8192;
            char* Bh = Ah + 16384;
            char* Bl = Ah + 24576;
#pragma unroll
            for (int q = 0; q < 4; q++) {
                uint32_t h01, l01, h23, l23;
                cvt_pair_hl(av[q].x, av[q].y, h01, l01);
                cvt_pair_hl(av[q].z, av[q].w, h23, l23);
                const uint32_t o = SWZ((uint32_t)(a_row * 64 + a_k0 * 2 + q * 8));
                *reinterpret_cast<uint2*>(Ah + o) = make_uint2(h01, h23);
                *reinterpret_cast<uint2*>(Al + o) = make_uint2(l01, l23);
            }
            float b0[4] = {bv[0].x, bv[0].y, bv[0].z, bv[0].w};
            float b1[4] = {bv[1].x, bv[1].y, bv[1].z, bv[1].w};
            float b2[4] = {bv[2].x, bv[2].y, bv[2].z, bv[2].w};
            float b3[4] = {bv[3].x, bv[3].y, bv[3].z, bv[3].w};
#pragma unroll
            for (int j = 0; j < 4; j++) {
                uint32_t h01, l01, h23, l23;
                cvt_pair_hl(b0[j], b1[j], h01, l01);
                cvt_pair_hl(b2[j], b3[j], h23, l23);
                const uint32_t o = SWZ((uint32_t)((b_n0 + j) * 64 + b_kb * 2));
                *reinterpret_cast<uint2*>(Bh + o) = make_uint2(h01, h23);
                *reinterpret_cast<uint2*>(Bl + o) = make_uint2(l01, l23);
            }
            __syncthreads();
        }
    }

    // ---- epilogue: out[tok, col] += w * (acc + be[e, col]) ----
    const int gid = lane >> 2;
    const int tig = lane & 3;
    const float* beRow = be + (size_t)e * DDIM + col0;
#pragma unroll
    for (int mt = 0; mt < 4; mt++) {
        const int  rA = m0 + mt * 16 + gid;
        const int  rB = rA + 8;
        const bool vA = rA < nvalid;
        const bool vB = rB < nvalid;
        const int   tokA = tok_s[rA];
        const int   tokB = tok_s[rB];
        const float wA = w_s[rA];
        const float wB = w_s[rB];
        float* oA = out + (size_t)tokA * DDIM + col0;
        float* oB = out + (size_t)tokB * DDIM + col0;
#pragma unroll
        for (int nt = 0; nt < 4; nt++) {
            const int c = n0w + nt * 8 + tig * 2;
            if (vA) {
                atomicAdd(oA + c,     wA * (acc[mt][nt][0] + beRow[c]));
                atomicAdd(oA + c + 1, wA * (acc[mt][nt][1] + beRow[c + 1]));
            }
            if (vB) {
                atomicAdd(oB + c,     wB * (acc[mt][nt][2] + beRow[c]));
                atomicAdd(oB + c + 1, wB * (acc[mt][nt][3] + beRow[c + 1]));
            }
        }
    }
}

// ---------------- launch ----------------
extern "C" void kernel_launch(void* const* d_in, const int* in_sizes, int n_in,
                              void* d_out, int out_size) {
    const float* x  = (const float*)d_in[0];
    const float* Wg = (const float*)d_in[1];
    const float* bg = (const float*)d_in[2];
    const float* We = (const float*)d_in[3];
    const float* be = (const float*)d_in[4];
    float* out = (float*)d_out;

    cudaFuncSetAttribute(moe_gemm_mma, cudaFuncAttributeMaxDynamicSharedMemorySize, SMEM_TOTAL);

    zero_cnt_kernel<<<1, 32>>>();
    gate_kernel<<<TOKENS / 8, 256>>>(x, Wg, bg);
    cudaMemsetAsync(out, 0, (size_t)out_size * sizeof(float));

    dim3 grid(TOKENS / BM, DDIM / BN, NEXP);   // (64, 8, 8); empty row tiles early-exit
    moe_gemm_mma<<<grid, 256, SMEM_TOTAL>>>(x, We, be, out);
}

// round 6
// speedup vs baseline: 2.2246x; 1.1362x over previous
#include <cuda_runtime.h>
#include <cuda_bf16.h>
#include <stdint.h>
#include <math.h>

#define TOKENS 8192
#define DDIM   1024
#define NEXP   8

#define BM 128
#define BN 128
#define BK 32
#define NKT (DDIM / BK)   // 32 k-chunks

// ---------------- scratch (allocation-free rule: __device__ globals) ----------------
__device__ int   g_cnt[NEXP];
__device__ int   g_tok[NEXP][TOKENS];
__device__ float g_wt [NEXP][TOKENS];
// pre-converted operands (bf16 two-term split)
__device__ __nv_bfloat16 g_xh[TOKENS * DDIM];
__device__ __nv_bfloat16 g_xl[TOKENS * DDIM];
__device__ __nv_bfloat16 g_Weh[NEXP * DDIM * DDIM];   // transposed: [e][n][k]
__device__ __nv_bfloat16 g_Wel[NEXP * DDIM * DDIM];

// ---------------- helpers ----------------
__device__ __forceinline__ uint32_t smem_u32(const void* p) {
    uint32_t a;
    asm("{ .reg .u64 t; cvta.to.shared.u64 t, %1; cvt.u32.u64 %0, t; }" : "=r"(a) : "l"(p));
    return a;
}

// XOR swizzle within a tile of rows x 64B: ldmatrix conflict-free.
#define SWZ(o) ((o) ^ ((((o) >> 7) & 3) << 4))

__device__ __forceinline__ void cvt_pair_hl(float va, float vb, uint32_t& hi, uint32_t& lo) {
    float ha = __bfloat162float(__float2bfloat16(va));
    float hb = __bfloat162float(__float2bfloat16(vb));
    asm("cvt.rn.bf16x2.f32 %0, %1, %2;" : "=r"(hi) : "f"(hb), "f"(ha));
    float la = va - ha, lb = vb - hb;
    asm("cvt.rn.bf16x2.f32 %0, %1, %2;" : "=r"(lo) : "f"(lb), "f"(la));
}

__device__ __forceinline__ void ldsm_x4(uint32_t* r, uint32_t addr) {
    asm volatile("ldmatrix.sync.aligned.m8n8.x4.shared.b16 {%0,%1,%2,%3}, [%4];"
                 : "=r"(r[0]), "=r"(r[1]), "=r"(r[2]), "=r"(r[3]) : "r"(addr));
}

__device__ __forceinline__ void mma_bf16(float* c, const uint32_t* a, uint32_t b0, uint32_t b1) {
    asm volatile("mma.sync.aligned.m16n8k16.row.col.f32.bf16.bf16.f32 "
                 "{%0,%1,%2,%3}, {%4,%5,%6,%7}, {%8,%9}, {%0,%1,%2,%3};"
                 : "+f"(c[0]), "+f"(c[1]), "+f"(c[2]), "+f"(c[3])
                 : "r"(a[0]), "r"(a[1]), "r"(a[2]), "r"(a[3]), "r"(b0), "r"(b1));
}

#define CP_ASYNC16(dst, src) \
    asm volatile("cp.async.cg.shared.global [%0], [%1], 16;" :: "r"(dst), "l"(src))
#define CP_COMMIT() asm volatile("cp.async.commit_group;" ::: "memory")
#define CP_WAIT(n)  asm volatile("cp.async.wait_group %0;" :: "n"(n) : "memory")

// ---------------- SMEM layout ----------------
// [0] tok_s 512 | [512] w_s 512 | [1024] stage0 (Ah 8K|Al 8K|Bh 8K|Bl 8K) | stage1
#define SM_TOK   0
#define SM_W     512
#define SM_TILE  1024
#define STAGE_BYTES 32768
#define SMEM_TOTAL (SM_TILE + 2 * STAGE_BYTES)   // 66560

// ---------------- prep kernels ----------------
__global__ void zero_cnt_kernel() {
    if (threadIdx.x < NEXP) g_cnt[threadIdx.x] = 0;
}

// x [t][d] fp32 -> bf16 hi/lo, same layout (coalesced)
__global__ void prep_x_kernel(const float* __restrict__ x) {
    const int i = blockIdx.x * 256 + threadIdx.x;     // 4 elems each
    float4 v = reinterpret_cast<const float4*>(x)[i];
    uint32_t h01, l01, h23, l23;
    cvt_pair_hl(v.x, v.y, h01, l01);
    cvt_pair_hl(v.z, v.w, h23, l23);
    reinterpret_cast<uint2*>(g_xh)[i] = make_uint2(h01, h23);
    reinterpret_cast<uint2*>(g_xl)[i] = make_uint2(l01, l23);
}

// We [e][k][n] fp32 -> transposed [e][n][k] bf16 hi/lo via 32x32 smem tiles
__global__ void prep_we_kernel(const float* __restrict__ We) {
    __shared__ float s[32][33];
    const int e  = blockIdx.z;
    const int n0 = blockIdx.x * 32;
    const int k0 = blockIdx.y * 32;
    const int tx = threadIdx.x & 31;
    const int ty = threadIdx.x >> 5;   // 0..7
    const float* src = We + ((size_t)e * DDIM + k0) * DDIM + n0;
#pragma unroll
    for (int i = 0; i < 4; i++)
        s[ty + i * 8][tx] = src[(size_t)(ty + i * 8) * DDIM + tx];
    __syncthreads();
#pragma unroll
    for (int i = 0; i < 4; i++) {
        const int nn = ty + i * 8;
        float v = s[tx][nn];
        __nv_bfloat16 h = __float2bfloat16(v);
        float hv = __bfloat162float(h);
        __nv_bfloat16 l = __float2bfloat16(v - hv);
        size_t o = ((size_t)e * DDIM + n0 + nn) * DDIM + k0 + tx;
        g_Weh[o] = h;
        g_Wel[o] = l;
    }
}

__global__ void gate_kernel(const float* __restrict__ x,
                            const float* __restrict__ Wg,
                            const float* __restrict__ bg) {
    int warp = threadIdx.x >> 5;
    int lane = threadIdx.x & 31;
    int t = blockIdx.x * 8 + warp;
    const float* xr = x + (size_t)t * DDIM;

    float acc[NEXP];
#pragma unroll
    for (int e = 0; e < NEXP; e++) acc[e] = 0.f;

    for (int d = lane; d < DDIM; d += 32) {
        float xv = xr[d];
        const float4* wr = reinterpret_cast<const float4*>(Wg + (size_t)d * NEXP);
        float4 w0 = wr[0];
        float4 w1 = wr[1];
        acc[0] += xv * w0.x; acc[1] += xv * w0.y;
        acc[2] += xv * w0.z; acc[3] += xv * w0.w;
        acc[4] += xv * w1.x; acc[5] += xv * w1.y;
        acc[6] += xv * w1.z; acc[7] += xv * w1.w;
    }
#pragma unroll
    for (int e = 0; e < NEXP; e++) {
#pragma unroll
        for (int o = 16; o > 0; o >>= 1)
            acc[e] += __shfl_down_sync(0xffffffffu, acc[e], o);
    }

    if (lane == 0) {
        float v1 = -INFINITY, v2 = -INFINITY;
        int   i1 = 0, i2 = 0;
#pragma unroll
        for (int e = 0; e < NEXP; e++) {
            float v = acc[e] + bg[e];
            if (v > v1)      { v2 = v1; i2 = i1; v1 = v; i1 = e; }
            else if (v > v2) { v2 = v;  i2 = e; }
        }
        float l     = __expf(v2 - v1);
        float denom = 1.f + l;
        float w1v   = 1.f / denom;
        float w2v   = l / denom;

        int p1 = atomicAdd(&g_cnt[i1], 1);
        g_tok[i1][p1] = t; g_wt[i1][p1] = w1v;
        int p2 = atomicAdd(&g_cnt[i2], 1);
        g_tok[i2][p2] = t; g_wt[i2][p2] = w2v;
    }
}

// ---------------- HMMA grouped GEMM (cp.async staging, pre-converted bf16) ----------------
__global__ __launch_bounds__(256, 1)
void moe_gemm_mma(const float* __restrict__ be,
                  float* __restrict__ out) {
    const int e    = blockIdx.z;
    const int n    = g_cnt[e];
    const int row0 = blockIdx.x * BM;
    if (row0 >= n) return;
    const int col0   = blockIdx.y * BN;
    const int nvalid = min(BM, n - row0);

    extern __shared__ char smem[];
    int*   tok_s = (int*)(smem + SM_TOK);
    float* w_s   = (float*)(smem + SM_W);
    const uint32_t tiles_u = smem_u32(smem + SM_TILE);

    const int tid  = threadIdx.x;
    const int lane = tid & 31;
    const int wid  = tid >> 5;

    if (tid < BM) {
        int tk = 0; float w = 0.f;
        if (tid < nvalid) { tk = g_tok[e][row0 + tid]; w = g_wt[e][row0 + tid]; }
        tok_s[tid] = tk;
        w_s[tid]   = w;
    }
    __syncthreads();

    // ---- cp.async staging assignment: 8 granules (16B) per thread per chunk ----
    const int g  = tid & 3;           // granule within 64B row
    const int r0 = tid >> 2;          // 0..63
    const int r1 = r0 + 64;           // 64..127
    const uint32_t oR0 = SWZ((uint32_t)(r0 * 64 + g * 16));
    const uint32_t oR1 = SWZ((uint32_t)(r1 * 64 + g * 16));

    const __nv_bfloat16* axh0 = g_xh + (size_t)tok_s[r0] * DDIM + g * 8;
    const __nv_bfloat16* axh1 = g_xh + (size_t)tok_s[r1] * DDIM + g * 8;
    const __nv_bfloat16* axl0 = g_xl + (size_t)tok_s[r0] * DDIM + g * 8;
    const __nv_bfloat16* axl1 = g_xl + (size_t)tok_s[r1] * DDIM + g * 8;
    const size_t bofs0 = ((size_t)e * DDIM + col0 + r0) * DDIM + g * 8;
    const size_t bofs1 = ((size_t)e * DDIM + col0 + r1) * DDIM + g * 8;
    const __nv_bfloat16* bwh0 = g_Weh + bofs0;
    const __nv_bfloat16* bwh1 = g_Weh + bofs1;
    const __nv_bfloat16* bwl0 = g_Wel + bofs0;
    const __nv_bfloat16* bwl1 = g_Wel + bofs1;

    // ---- compute assignment: warp tile 64x32 ----
    const int m0  = (wid & 1) * 64;
    const int n0w = (wid >> 1) * 32;
    const int a_lrow = (lane & 7) + ((lane >> 3) & 1) * 8;
    const int a_lk   = ((lane >> 4) & 1) * 8;
    const int b_lrow = (lane & 7) + ((lane >> 4) & 1) * 8;
    const int b_lk   = ((lane >> 3) & 1) * 8;

    float acc[4][4][4];
#pragma unroll
    for (int i = 0; i < 4; i++)
#pragma unroll
        for (int j = 0; j < 4; j++)
#pragma unroll
            for (int q = 0; q < 4; q++) acc[i][j][q] = 0.f;

    // stage chunk 0
    {
        const uint32_t base = tiles_u;
        CP_ASYNC16(base + oR0,          axh0);
        CP_ASYNC16(base + oR1,          axh1);
        CP_ASYNC16(base +  8192 + oR0,  axl0);
        CP_ASYNC16(base +  8192 + oR1,  axl1);
        CP_ASYNC16(base + 16384 + oR0,  bwh0);
        CP_ASYNC16(base + 16384 + oR1,  bwh1);
        CP_ASYNC16(base + 24576 + oR0,  bwl0);
        CP_ASYNC16(base + 24576 + oR1,  bwl1);
        CP_COMMIT();
    }

    for (int kt = 0; kt < NKT; kt++) {
        // stage next chunk into other buffer
        if (kt + 1 < NKT) {
            const int kk = (kt + 1) * BK;
            const uint32_t base = tiles_u + ((kt + 1) & 1) * STAGE_BYTES;
            CP_ASYNC16(base + oR0,          axh0 + kk);
            CP_ASYNC16(base + oR1,          axh1 + kk);
            CP_ASYNC16(base +  8192 + oR0,  axl0 + kk);
            CP_ASYNC16(base +  8192 + oR1,  axl1 + kk);
            CP_ASYNC16(base + 16384 + oR0,  bwh0 + kk);
            CP_ASYNC16(base + 16384 + oR1,  bwh1 + kk);
            CP_ASYNC16(base + 24576 + oR0,  bwl0 + kk);
            CP_ASYNC16(base + 24576 + oR1,  bwl1 + kk);
            CP_COMMIT();
            CP_WAIT(1);            // chunk kt complete
        } else {
            CP_WAIT(0);
        }
        __syncthreads();

        // ---- compute on buffer kt&1 ----
        const uint32_t AhU = tiles_u + (kt & 1) * STAGE_BYTES;
        const uint32_t BhU = AhU + 16384;
#pragma unroll
        for (int ks = 0; ks < 2; ks++) {
            uint32_t ah[4][4], al[4][4], bh[2][4], bl[2][4];
#pragma unroll
            for (int mt = 0; mt < 4; mt++) {
                const uint32_t o = SWZ((uint32_t)((m0 + mt * 16 + a_lrow) * 64 +
                                                  (ks * 16 + a_lk) * 2));
                ldsm_x4(ah[mt], AhU + o);
                ldsm_x4(al[mt], AhU + 8192 + o);
            }
#pragma unroll
            for (int bp = 0; bp < 2; bp++) {
                const uint32_t o = SWZ((uint32_t)((n0w + bp * 16 + b_lrow) * 64 +
                                                  (ks * 16 + b_lk) * 2));
                ldsm_x4(bh[bp], BhU + o);
                ldsm_x4(bl[bp], BhU + 8192 + o);
            }
            // pass-outer: same-acc MMAs are 16 apart (no HMMA RAW stalls)
#pragma unroll
            for (int mt = 0; mt < 4; mt++)
#pragma unroll
                for (int nt = 0; nt < 4; nt++) {
                    const int bp = nt >> 1, bo = (nt & 1) * 2;
                    mma_bf16(acc[mt][nt], ah[mt], bh[bp][bo], bh[bp][bo + 1]);
                }
#pragma unroll
            for (int mt = 0; mt < 4; mt++)
#pragma unroll
                for (int nt = 0; nt < 4; nt++) {
                    const int bp = nt >> 1, bo = (nt & 1) * 2;
                    mma_bf16(acc[mt][nt], ah[mt], bl[bp][bo], bl[bp][bo + 1]);
                }
#pragma unroll
            for (int mt = 0; mt < 4; mt++)
#pragma unroll
                for (int nt = 0; nt < 4; nt++) {
                    const int bp = nt >> 1, bo = (nt & 1) * 2;
                    mma_bf16(acc[mt][nt], al[mt], bh[bp][bo], bh[bp][bo + 1]);
                }
        }
        __syncthreads();   // buffer kt&1 consumed; safe to restage next iter
    }

    // ---- epilogue: out[tok, col] += w * (acc + be[e, col]) ----
    const int gid = lane >> 2;
    const int tig = lane & 3;
    const float* beRow = be + (size_t)e * DDIM + col0;
#pragma unroll
    for (int mt = 0; mt < 4; mt++) {
        const int  rA = m0 + mt * 16 + gid;
        const int  rB = rA + 8;
        const bool vA = rA < nvalid;
        const bool vB = rB < nvalid;
        const int   tokA = tok_s[rA];
        const int   tokB = tok_s[rB];
        const float wA = w_s[rA];
        const float wB = w_s[rB];
        float* oA = out + (size_t)tokA * DDIM + col0;
        float* oB = out + (size_t)tokB * DDIM + col0;
#pragma unroll
        for (int nt = 0; nt < 4; nt++) {
            const int c = n0w + nt * 8 + tig * 2;
            if (vA) {
                atomicAdd(oA + c,     wA * (acc[mt][nt][0] + beRow[c]));
                atomicAdd(oA + c + 1, wA * (acc[mt][nt][1] + beRow[c + 1]));
            }
            if (vB) {
                atomicAdd(oB + c,     wB * (acc[mt][nt][2] + beRow[c]));
                atomicAdd(oB + c + 1, wB * (acc[mt][nt][3] + beRow[c + 1]));
            }
        }
    }
}

// ---------------- launch ----------------
extern "C" void kernel_launch(void* const* d_in, const int* in_sizes, int n_in,
                              void* d_out, int out_size) {
    const float* x  = (const float*)d_in[0];
    const float* Wg = (const float*)d_in[1];
    const float* bg = (const float*)d_in[2];
    const float* We = (const float*)d_in[3];
    const float* be = (const float*)d_in[4];
    float* out = (float*)d_out;

    cudaFuncSetAttribute(moe_gemm_mma, cudaFuncAttributeMaxDynamicSharedMemorySize, SMEM_TOTAL);

    zero_cnt_kernel<<<1, 32>>>();
    prep_x_kernel<<<TOKENS * DDIM / 4 / 256, 256>>>(x);
    prep_we_kernel<<<dim3(DDIM / 32, DDIM / 32, NEXP), 256>>>(We);
    gate_kernel<<<TOKENS / 8, 256>>>(x, Wg, bg);
    cudaMemsetAsync(out, 0, (size_t)out_size * sizeof(float));

    dim3 grid(TOKENS / BM, DDIM / BN, NEXP);   // empty row tiles early-exit
    moe_gemm_mma<<<grid, 256, SMEM_TOTAL>>>(be, out);
}

// round 7
// speedup vs baseline: 3.0496x; 1.3709x over previous
#include <cuda_runtime.h>
#include <cuda_fp16.h>
#include <stdint.h>
#include <math.h>

#define TOKENS 8192
#define DDIM   1024
#define NEXP   8

#define BM 128
#define BN 128
#define BK 32
#define NKT (DDIM / BK)   // 32 k-chunks

// ---------------- scratch (allocation-free rule: __device__ globals) ----------------
__device__ int   g_cnt[NEXP];
__device__ int   g_tok[NEXP][TOKENS];
__device__ float g_wt [NEXP][TOKENS];
// pre-converted fp16 operands
__device__ __half g_xh[TOKENS * DDIM];
__device__ __half g_Weh[NEXP * DDIM * DDIM];   // transposed: [e][n][k]

// ---------------- helpers ----------------
__device__ __forceinline__ uint32_t smem_u32(const void* p) {
    uint32_t a;
    asm("{ .reg .u64 t; cvta.to.shared.u64 t, %1; cvt.u32.u64 %0, t; }" : "=r"(a) : "l"(p));
    return a;
}

// XOR swizzle within a tile of 128 rows x 64B: ldmatrix conflict-free.
#define SWZ(o) ((o) ^ ((((o) >> 7) & 3) << 4))

__device__ __forceinline__ void ldsm_x4(uint32_t* r, uint32_t addr) {
    asm volatile("ldmatrix.sync.aligned.m8n8.x4.shared.b16 {%0,%1,%2,%3}, [%4];"
                 : "=r"(r[0]), "=r"(r[1]), "=r"(r[2]), "=r"(r[3]) : "r"(addr));
}

__device__ __forceinline__ void mma_fp16(float* c, const uint32_t* a, uint32_t b0, uint32_t b1) {
    asm volatile("mma.sync.aligned.m16n8k16.row.col.f32.f16.f16.f32 "
                 "{%0,%1,%2,%3}, {%4,%5,%6,%7}, {%8,%9}, {%0,%1,%2,%3};"
                 : "+f"(c[0]), "+f"(c[1]), "+f"(c[2]), "+f"(c[3])
                 : "r"(a[0]), "r"(a[1]), "r"(a[2]), "r"(a[3]), "r"(b0), "r"(b1));
}

#define CP_ASYNC16(dst, src) \
    asm volatile("cp.async.cg.shared.global [%0], [%1], 16;" :: "r"(dst), "l"(src))
#define CP_COMMIT() asm volatile("cp.async.commit_group;" ::: "memory")
#define CP_WAIT(n)  asm volatile("cp.async.wait_group %0;" :: "n"(n) : "memory")

// ---------------- SMEM layout ----------------
// [0] tok_s 512 | [512] w_s 512 | [1024] stage0 (A 8K | B 8K) | stage1
#define SM_TOK   0
#define SM_W     512
#define SM_TILE  1024
#define STAGE_BYTES 16384
#define SMEM_TOTAL (SM_TILE + 2 * STAGE_BYTES)   // 33792

// ---------------- prep kernels ----------------
__global__ void zero_cnt_kernel() {
    if (threadIdx.x < NEXP) g_cnt[threadIdx.x] = 0;
}

// x [t][d] fp32 -> fp16, same layout (coalesced)
__global__ void prep_x_kernel(const float* __restrict__ x) {
    const int i = blockIdx.x * 256 + threadIdx.x;     // one float4 each
    float4 v = reinterpret_cast<const float4*>(x)[i];
    __half2 h01 = __float22half2_rn(make_float2(v.x, v.y));
    __half2 h23 = __float22half2_rn(make_float2(v.z, v.w));
    reinterpret_cast<uint2*>(g_xh)[i] =
        make_uint2(*reinterpret_cast<uint32_t*>(&h01), *reinterpret_cast<uint32_t*>(&h23));
}

// We [e][k][n] fp32 -> transposed [e][n][k] fp16 via 32x32 smem tiles
__global__ void prep_we_kernel(const float* __restrict__ We) {
    __shared__ float s[32][33];
    const int e  = blockIdx.z;
    const int n0 = blockIdx.x * 32;
    const int k0 = blockIdx.y * 32;
    const int tx = threadIdx.x & 31;
    const int ty = threadIdx.x >> 5;   // 0..7
    const float* src = We + ((size_t)e * DDIM + k0) * DDIM + n0;
#pragma unroll
    for (int i = 0; i < 4; i++)
        s[ty + i * 8][tx] = src[(size_t)(ty + i * 8) * DDIM + tx];
    __syncthreads();
#pragma unroll
    for (int i = 0; i < 4; i++) {
        const int nn = ty + i * 8;
        size_t o = ((size_t)e * DDIM + n0 + nn) * DDIM + k0 + tx;
        g_Weh[o] = __float2half_rn(s[tx][nn]);
    }
}

__global__ void gate_kernel(const float* __restrict__ x,
                            const float* __restrict__ Wg,
                            const float* __restrict__ bg) {
    int warp = threadIdx.x >> 5;
    int lane = threadIdx.x & 31;
    int t = blockIdx.x * 8 + warp;
    const float4* x4 = reinterpret_cast<const float4*>(x + (size_t)t * DDIM);
    const float4* w4 = reinterpret_cast<const float4*>(Wg);

    float acc[NEXP];
#pragma unroll
    for (int e = 0; e < NEXP; e++) acc[e] = 0.f;

#pragma unroll
    for (int i = 0; i < 8; i++) {
        const int f = i * 32 + lane;      // float4 index; d = 4f
        float4 xv = x4[f];
        float xs[4] = {xv.x, xv.y, xv.z, xv.w};
#pragma unroll
        for (int j = 0; j < 4; j++) {
            float4 w0 = w4[(f * 4 + j) * 2];
            float4 w1 = w4[(f * 4 + j) * 2 + 1];
            acc[0] += xs[j] * w0.x; acc[1] += xs[j] * w0.y;
            acc[2] += xs[j] * w0.z; acc[3] += xs[j] * w0.w;
            acc[4] += xs[j] * w1.x; acc[5] += xs[j] * w1.y;
            acc[6] += xs[j] * w1.z; acc[7] += xs[j] * w1.w;
        }
    }
#pragma unroll
    for (int e = 0; e < NEXP; e++) {
#pragma unroll
        for (int o = 16; o > 0; o >>= 1)
            acc[e] += __shfl_down_sync(0xffffffffu, acc[e], o);
    }

    if (lane == 0) {
        float v1 = -INFINITY, v2 = -INFINITY;
        int   i1 = 0, i2 = 0;
#pragma unroll
        for (int e = 0; e < NEXP; e++) {
            float v = acc[e] + bg[e];
            if (v > v1)      { v2 = v1; i2 = i1; v1 = v; i1 = e; }
            else if (v > v2) { v2 = v;  i2 = e; }
        }
        float l     = __expf(v2 - v1);
        float denom = 1.f + l;
        float w1v   = 1.f / denom;
        float w2v   = l / denom;

        int p1 = atomicAdd(&g_cnt[i1], 1);
        g_tok[i1][p1] = t; g_wt[i1][p1] = w1v;
        int p2 = atomicAdd(&g_cnt[i2], 1);
        g_tok[i2][p2] = t; g_wt[i2][p2] = w2v;
    }
}

// ---------------- HMMA grouped GEMM (fp16 single-pass, cp.async staging) ----------------
__global__ __launch_bounds__(256, 1)
void moe_gemm_mma(const float* __restrict__ be,
                  float* __restrict__ out) {
    const int e    = blockIdx.z;
    const int n    = g_cnt[e];
    const int row0 = blockIdx.x * BM;
    if (row0 >= n) return;
    const int col0   = blockIdx.y * BN;
    const int nvalid = min(BM, n - row0);

    extern __shared__ char smem[];
    int*   tok_s = (int*)(smem + SM_TOK);
    float* w_s   = (float*)(smem + SM_W);
    const uint32_t tiles_u = smem_u32(smem + SM_TILE);

    const int tid  = threadIdx.x;
    const int lane = tid & 31;
    const int wid  = tid >> 5;

    if (tid < BM) {
        int tk = 0; float w = 0.f;
        if (tid < nvalid) { tk = g_tok[e][row0 + tid]; w = g_wt[e][row0 + tid]; }
        tok_s[tid] = tk;
        w_s[tid]   = w;
    }
    __syncthreads();

    // ---- cp.async staging: 4 granules (16B) per thread per chunk ----
    const int g  = tid & 3;           // granule within 64B row
    const int r0 = tid >> 2;          // 0..63
    const int r1 = r0 + 64;           // 64..127
    const uint32_t oR0 = SWZ((uint32_t)(r0 * 64 + g * 16));
    const uint32_t oR1 = SWZ((uint32_t)(r1 * 64 + g * 16));

    const __half* ax0 = g_xh + (size_t)tok_s[r0] * DDIM + g * 8;
    const __half* ax1 = g_xh + (size_t)tok_s[r1] * DDIM + g * 8;
    const __half* bw0 = g_Weh + ((size_t)e * DDIM + col0 + r0) * DDIM + g * 8;
    const __half* bw1 = g_Weh + ((size_t)e * DDIM + col0 + r1) * DDIM + g * 8;

    // ---- compute assignment: warp tile 64x32 ----
    const int m0  = (wid & 1) * 64;
    const int n0w = (wid >> 1) * 32;
    const int a_lrow = (lane & 7) + ((lane >> 3) & 1) * 8;
    const int a_lk   = ((lane >> 4) & 1) * 8;
    const int b_lrow = (lane & 7) + ((lane >> 4) & 1) * 8;
    const int b_lk   = ((lane >> 3) & 1) * 8;

    float acc[4][4][4];
#pragma unroll
    for (int i = 0; i < 4; i++)
#pragma unroll
        for (int j = 0; j < 4; j++)
#pragma unroll
            for (int q = 0; q < 4; q++) acc[i][j][q] = 0.f;

    // stage chunk 0
    {
        const uint32_t base = tiles_u;
        CP_ASYNC16(base + oR0,        ax0);
        CP_ASYNC16(base + oR1,        ax1);
        CP_ASYNC16(base + 8192 + oR0, bw0);
        CP_ASYNC16(base + 8192 + oR1, bw1);
        CP_COMMIT();
    }

    for (int kt = 0; kt < NKT; kt++) {
        if (kt + 1 < NKT) {
            const int kk = (kt + 1) * BK;
            const uint32_t base = tiles_u + ((kt + 1) & 1) * STAGE_BYTES;
            CP_ASYNC16(base + oR0,        ax0 + kk);
            CP_ASYNC16(base + oR1,        ax1 + kk);
            CP_ASYNC16(base + 8192 + oR0, bw0 + kk);
            CP_ASYNC16(base + 8192 + oR1, bw1 + kk);
            CP_COMMIT();
            CP_WAIT(1);            // chunk kt complete
        } else {
            CP_WAIT(0);
        }
        __syncthreads();

        // ---- compute on buffer kt&1 ----
        const uint32_t AU = tiles_u + (kt & 1) * STAGE_BYTES;
        const uint32_t BU = AU + 8192;
#pragma unroll
        for (int ks = 0; ks < 2; ks++) {
            uint32_t ah[4][4], bh[2][4];
#pragma unroll
            for (int mt = 0; mt < 4; mt++) {
                const uint32_t o = SWZ((uint32_t)((m0 + mt * 16 + a_lrow) * 64 +
                                                  (ks * 16 + a_lk) * 2));
                ldsm_x4(ah[mt], AU + o);
            }
#pragma unroll
            for (int bp = 0; bp < 2; bp++) {
                const uint32_t o = SWZ((uint32_t)((n0w + bp * 16 + b_lrow) * 64 +
                                                  (ks * 16 + b_lk) * 2));
                ldsm_x4(bh[bp], BU + o);
            }
#pragma unroll
            for (int mt = 0; mt < 4; mt++)
#pragma unroll
                for (int nt = 0; nt < 4; nt++) {
                    const int bp = nt >> 1, bo = (nt & 1) * 2;
                    mma_fp16(acc[mt][nt], ah[mt], bh[bp][bo], bh[bp][bo + 1]);
                }
        }
        __syncthreads();   // buffer kt&1 consumed; safe to restage next iter
    }

    // ---- epilogue: out[tok, col] += w * (acc + be[e, col]) ----
    const int gid = lane >> 2;
    const int tig = lane & 3;
    const float* beRow = be + (size_t)e * DDIM + col0;
#pragma unroll
    for (int mt = 0; mt < 4; mt++) {
        const int  rA = m0 + mt * 16 + gid;
        const int  rB = rA + 8;
        const bool vA = rA < nvalid;
        const bool vB = rB < nvalid;
        const int   tokA = tok_s[rA];
        const int   tokB = tok_s[rB];
        const float wA = w_s[rA];
        const float wB = w_s[rB];
        float* oA = out + (size_t)tokA * DDIM + col0;
        float* oB = out + (size_t)tokB * DDIM + col0;
#pragma unroll
        for (int nt = 0; nt < 4; nt++) {
            const int c = n0w + nt * 8 + tig * 2;
            if (vA) {
                atomicAdd(oA + c,     wA * (acc[mt][nt][0] + beRow[c]));
                atomicAdd(oA + c + 1, wA * (acc[mt][nt][1] + beRow[c + 1]));
            }
            if (vB) {
                atomicAdd(oB + c,     wB * (acc[mt][nt][2] + beRow[c]));
                atomicAdd(oB + c + 1, wB * (acc[mt][nt][3] + beRow[c + 1]));
            }
        }
    }
}

// ---------------- launch ----------------
extern "C" void kernel_launch(void* const* d_in, const int* in_sizes, int n_in,
                              void* d_out, int out_size) {
    const float* x  = (const float*)d_in[0];
    const float* Wg = (const float*)d_in[1];
    const float* bg = (const float*)d_in[2];
    const float* We = (const float*)d_in[3];
    const float* be = (const float*)d_in[4];
    float* out = (float*)d_out;

    cudaFuncSetAttribute(moe_gemm_mma, cudaFuncAttributeMaxDynamicSharedMemorySize, SMEM_TOTAL);

    zero_cnt_kernel<<<1, 32>>>();
    prep_x_kernel<<<TOKENS * DDIM / 4 / 256, 256>>>(x);
    prep_we_kernel<<<dim3(DDIM / 32, DDIM / 32, NEXP), 256>>>(We);
    gate_kernel<<<TOKENS / 8, 256>>>(x, Wg, bg);
    cudaMemsetAsync(out, 0, (size_t)out_size * sizeof(float));

    dim3 grid(TOKENS / BM, DDIM / BN, NEXP);   // empty row tiles early-exit
    moe_gemm_mma<<<grid, 256, SMEM_TOTAL>>>(be, out);
}

// round 8
// speedup vs baseline: 3.9055x; 1.2807x over previous
#include <cuda_runtime.h>
#include <cuda_fp16.h>
#include <stdint.h>
#include <math.h>

#define TOKENS 8192
#define DDIM   1024
#define NEXP   8

#define BM 128
#define BN 256
#define BK 64
#define NKT (DDIM / BK)   // 16 k-chunks

// ---------------- scratch (allocation-free rule: __device__ globals) ----------------
__device__ int   g_cnt[NEXP];
__device__ int   g_tok[NEXP][TOKENS];    // packed: token*2 + slot
__device__ float g_wt [NEXP][TOKENS];
__device__ __half g_xh[TOKENS * DDIM];
__device__ __half g_Weh[NEXP * DDIM * DDIM];   // transposed: [e][n][k]
__device__ float g_scr[2 * TOKENS * DDIM];     // per-slot contributions

// ---------------- helpers ----------------
__device__ __forceinline__ uint32_t smem_u32(const void* p) {
    uint32_t a;
    asm("{ .reg .u64 t; cvta.to.shared.u64 t, %1; cvt.u32.u64 %0, t; }" : "=r"(a) : "l"(p));
    return a;
}

// SW128 swizzle for 128B rows (Swizzle<3,4,3>)
#define SWZ(o) ((o) ^ (((o) >> 3) & 0x70))

__device__ __forceinline__ void ldsm_x4(uint32_t* r, uint32_t addr) {
    asm volatile("ldmatrix.sync.aligned.m8n8.x4.shared.b16 {%0,%1,%2,%3}, [%4];"
                 : "=r"(r[0]), "=r"(r[1]), "=r"(r[2]), "=r"(r[3]) : "r"(addr));
}

__device__ __forceinline__ void mma_fp16(float* c, const uint32_t* a, uint32_t b0, uint32_t b1) {
    asm volatile("mma.sync.aligned.m16n8k16.row.col.f32.f16.f16.f32 "
                 "{%0,%1,%2,%3}, {%4,%5,%6,%7}, {%8,%9}, {%0,%1,%2,%3};"
                 : "+f"(c[0]), "+f"(c[1]), "+f"(c[2]), "+f"(c[3])
                 : "r"(a[0]), "r"(a[1]), "r"(a[2]), "r"(a[3]), "r"(b0), "r"(b1));
}

#define CP_ASYNC16(dst, src) \
    asm volatile("cp.async.cg.shared.global [%0], [%1], 16;" :: "r"(dst), "l"(src))
#define CP_COMMIT() asm volatile("cp.async.commit_group;" ::: "memory")
#define CP_WAIT(n)  asm volatile("cp.async.wait_group %0;" :: "n"(n) : "memory")

// ---------------- SMEM layout ----------------
// [0] ent_s 512 | [512] w_s 512 | [1024] 3 stages of (A 16K | B 32K)
#define SM_ENT   0
#define SM_W     512
#define SM_TILE  1024
#define A_BYTES  16384
#define STAGE_BYTES 49152
#define SMEM_TOTAL (SM_TILE + 3 * STAGE_BYTES)   // 148480

// ---------------- prep kernels ----------------
__global__ void zero_cnt_kernel() {
    if (threadIdx.x < NEXP) g_cnt[threadIdx.x] = 0;
}

__global__ void prep_x_kernel(const float* __restrict__ x) {
    const int i = blockIdx.x * 256 + threadIdx.x;     // one float4 each
    float4 v = reinterpret_cast<const float4*>(x)[i];
    __half2 h01 = __float22half2_rn(make_float2(v.x, v.y));
    __half2 h23 = __float22half2_rn(make_float2(v.z, v.w));
    reinterpret_cast<uint2*>(g_xh)[i] =
        make_uint2(*reinterpret_cast<uint32_t*>(&h01), *reinterpret_cast<uint32_t*>(&h23));
}

__global__ void prep_we_kernel(const float* __restrict__ We) {
    __shared__ float s[32][33];
    const int e  = blockIdx.z;
    const int n0 = blockIdx.x * 32;
    const int k0 = blockIdx.y * 32;
    const int tx = threadIdx.x & 31;
    const int ty = threadIdx.x >> 5;   // 0..7
    const float* src = We + ((size_t)e * DDIM + k0) * DDIM + n0;
#pragma unroll
    for (int i = 0; i < 4; i++)
        s[ty + i * 8][tx] = src[(size_t)(ty + i * 8) * DDIM + tx];
    __syncthreads();
#pragma unroll
    for (int i = 0; i < 4; i++) {
        const int nn = ty + i * 8;
        size_t o = ((size_t)e * DDIM + n0 + nn) * DDIM + k0 + tx;
        g_Weh[o] = __float2half_rn(s[tx][nn]);
    }
}

// warp handles 8 tokens; Wg slab held in registers, reused across tokens
__global__ __launch_bounds__(256)
void gate_kernel(const float* __restrict__ x,
                 const float* __restrict__ Wg,
                 const float* __restrict__ bg) {
    const int warp = threadIdx.x >> 5;
    const int lane = threadIdx.x & 31;
    const int t0 = (blockIdx.x * 8 + warp) * 8;

    float acc[8][NEXP];
#pragma unroll
    for (int tt = 0; tt < 8; tt++)
#pragma unroll
        for (int e = 0; e < NEXP; e++) acc[tt][e] = 0.f;

#pragma unroll
    for (int s = 0; s < 4; s++) {      // 4 slabs of 256 d
        float wg[8][NEXP];
#pragma unroll
        for (int i = 0; i < 8; i++) {
            const float4* wr = reinterpret_cast<const float4*>(
                Wg + (size_t)(s * 256 + i * 32 + lane) * NEXP);
            float4 w0 = wr[0], w1 = wr[1];
            wg[i][0] = w0.x; wg[i][1] = w0.y; wg[i][2] = w0.z; wg[i][3] = w0.w;
            wg[i][4] = w1.x; wg[i][5] = w1.y; wg[i][6] = w1.z; wg[i][7] = w1.w;
        }
#pragma unroll
        for (int tt = 0; tt < 8; tt++) {
            const float* xr = x + (size_t)(t0 + tt) * DDIM + s * 256 + lane;
#pragma unroll
            for (int i = 0; i < 8; i++) {
                float xv = xr[i * 32];
#pragma unroll
                for (int e = 0; e < NEXP; e++) acc[tt][e] += xv * wg[i][e];
            }
        }
    }

#pragma unroll
    for (int tt = 0; tt < 8; tt++) {
        float v[NEXP];
#pragma unroll
        for (int e = 0; e < NEXP; e++) {
            float r = acc[tt][e];
#pragma unroll
            for (int o = 16; o > 0; o >>= 1) r += __shfl_down_sync(0xffffffffu, r, o);
            v[e] = r;
        }
        if (lane == 0) {
            float v1 = -INFINITY, v2 = -INFINITY;
            int   i1 = 0, i2 = 0;
#pragma unroll
            for (int e = 0; e < NEXP; e++) {
                float s2 = v[e] + bg[e];
                if (s2 > v1)      { v2 = v1; i2 = i1; v1 = s2; i1 = e; }
                else if (s2 > v2) { v2 = s2; i2 = e; }
            }
            float l     = __expf(v2 - v1);
            float denom = 1.f + l;
            const int t = t0 + tt;
            int p1 = atomicAdd(&g_cnt[i1], 1);
            g_tok[i1][p1] = t * 2 + 0; g_wt[i1][p1] = 1.f / denom;
            int p2 = atomicAdd(&g_cnt[i2], 1);
            g_tok[i2][p2] = t * 2 + 1; g_wt[i2][p2] = l / denom;
        }
    }
}

// ---------------- HMMA grouped GEMM (fp16, 3-stage cp.async, slot-scratch out) ----------------
__global__ __launch_bounds__(256, 1)
void moe_gemm_mma(const float* __restrict__ be) {
    const int e    = blockIdx.z;
    const int n    = g_cnt[e];
    const int row0 = blockIdx.x * BM;
    if (row0 >= n) return;
    const int col0   = blockIdx.y * BN;
    const int nvalid = min(BM, n - row0);

    extern __shared__ char smem[];
    int*   ent_s = (int*)(smem + SM_ENT);
    float* w_s   = (float*)(smem + SM_W);
    const uint32_t tiles_u = smem_u32(smem + SM_TILE);

    const int tid  = threadIdx.x;
    const int lane = tid & 31;
    const int wid  = tid >> 5;

    if (tid < BM) {
        int tk = 0; float w = 0.f;
        if (tid < nvalid) { tk = g_tok[e][row0 + tid]; w = g_wt[e][row0 + tid]; }
        ent_s[tid] = tk;
        w_s[tid]   = w;
    }
    __syncthreads();

    // ---- staging: thread covers granules (sh..sh+3) of A row sr, B rows sr & sr+128
    const int sr = tid >> 1;
    const int sh = (tid & 1) * 4;
    uint32_t og[4];
#pragma unroll
    for (int q = 0; q < 4; q++)
        og[q] = SWZ((uint32_t)(sr * 128 + (sh + q) * 16));

    const __half* aS  = g_xh + (size_t)(ent_s[sr] >> 1) * DDIM + sh * 8;
    const __half* bS0 = g_Weh + ((size_t)e * DDIM + col0 + sr) * DDIM + sh * 8;
    const __half* bS1 = bS0 + (size_t)128 * DDIM;

    // ---- compute assignment: warp tile 64x64
    const int m0  = (wid & 1) * 64;
    const int n0w = (wid >> 1) * 64;
    const int a_lrow = (lane & 7) + ((lane >> 3) & 1) * 8;
    const int a_lk   = ((lane >> 4) & 1) * 8;
    const int b_lrow = (lane & 7) + ((lane >> 4) & 1) * 8;
    const int b_lk   = ((lane >> 3) & 1) * 8;

    float acc[4][8][4];
#pragma unroll
    for (int i = 0; i < 4; i++)
#pragma unroll
        for (int j = 0; j < 8; j++)
#pragma unroll
            for (int q = 0; q < 4; q++) acc[i][j][q] = 0.f;

    // prologue: stage chunks 0,1
#pragma unroll
    for (int pc = 0; pc < 2; pc++) {
        const uint32_t base = tiles_u + pc * STAGE_BYTES;
        const int kk = pc * BK;
#pragma unroll
        for (int q = 0; q < 4; q++) CP_ASYNC16(base + og[q], aS + kk + q * 8);
#pragma unroll
        for (int q = 0; q < 4; q++) CP_ASYNC16(base + A_BYTES + og[q], bS0 + kk + q * 8);
#pragma unroll
        for (int q = 0; q < 4; q++) CP_ASYNC16(base + A_BYTES + 16384 + og[q], bS1 + kk + q * 8);
        CP_COMMIT();
    }

    for (int kt = 0; kt < NKT; kt++) {
        if (kt + 1 < NKT) { CP_WAIT(1); } else { CP_WAIT(0); }
        __syncthreads();   // chunk kt visible to all; all warps done with chunk kt-1

        if (kt + 2 < NKT) {
            const uint32_t base = tiles_u + ((kt + 2) % 3) * STAGE_BYTES;
            const int kk = (kt + 2) * BK;
#pragma unroll
            for (int q = 0; q < 4; q++) CP_ASYNC16(base + og[q], aS + kk + q * 8);
#pragma unroll
            for (int q = 0; q < 4; q++) CP_ASYNC16(base + A_BYTES + og[q], bS0 + kk + q * 8);
#pragma unroll
            for (int q = 0; q < 4; q++) CP_ASYNC16(base + A_BYTES + 16384 + og[q], bS1 + kk + q * 8);
            CP_COMMIT();
        }

        const uint32_t AU = tiles_u + (kt % 3) * STAGE_BYTES;
        const uint32_t BU = AU + A_BYTES;
#pragma unroll
        for (int ks = 0; ks < 4; ks++) {
            uint32_t ah[4][4], bh[4][4];
#pragma unroll
            for (int mt = 0; mt < 4; mt++) {
                const uint32_t o = SWZ((uint32_t)((m0 + mt * 16 + a_lrow) * 128 +
                                                  (ks * 16 + a_lk) * 2));
                ldsm_x4(ah[mt], AU + o);
            }
#pragma unroll
            for (int np = 0; np < 4; np++) {
                const uint32_t o = SWZ((uint32_t)((n0w + np * 16 + b_lrow) * 128 +
                                                  (ks * 16 + b_lk) * 2));
                ldsm_x4(bh[np], BU + o);
            }
#pragma unroll
            for (int mt = 0; mt < 4; mt++)
#pragma unroll
                for (int nt = 0; nt < 8; nt++) {
                    const int bp = nt >> 1, bo = (nt & 1) * 2;
                    mma_fp16(acc[mt][nt], ah[mt], bh[bp][bo], bh[bp][bo + 1]);
                }
        }
    }

    // ---- epilogue: scr[slot][token][col] = w * (acc + be[e][col]), plain stores
    const int gid = lane >> 2;
    const int tig = lane & 3;
    const float* beRow = be + (size_t)e * DDIM + col0;
#pragma unroll
    for (int mt = 0; mt < 4; mt++) {
        const int  rA = m0 + mt * 16 + gid;
        const int  rB = rA + 8;
        const bool vA = rA < nvalid;
        const bool vB = rB < nvalid;
        const int  entA = ent_s[rA];
        const int  entB = ent_s[rB];
        const float wA = w_s[rA];
        const float wB = w_s[rB];
        float* sA = g_scr + ((size_t)(entA >> 1) + (size_t)(entA & 1) * TOKENS) * DDIM + col0;
        float* sB = g_scr + ((size_t)(entB >> 1) + (size_t)(entB & 1) * TOKENS) * DDIM + col0;
#pragma unroll
        for (int nt = 0; nt < 8; nt++) {
            const int c = n0w + nt * 8 + tig * 2;
            const float2 bev = *reinterpret_cast<const float2*>(beRow + c);
            if (vA) {
                float2 v = make_float2(wA * (acc[mt][nt][0] + bev.x),
                                       wA * (acc[mt][nt][1] + bev.y));
                *reinterpret_cast<float2*>(sA + c) = v;
            }
            if (vB) {
                float2 v = make_float2(wB * (acc[mt][nt][2] + bev.x),
                                       wB * (acc[mt][nt][3] + bev.y));
                *reinterpret_cast<float2*>(sB + c) = v;
            }
        }
    }
}

__global__ void combine_kernel(float* __restrict__ out) {
    const size_t i = (size_t)blockIdx.x * 256 + threadIdx.x;   // float4 units
    const float4* s = reinterpret_cast<const float4*>(g_scr);
    float4 a = s[i];
    float4 b = s[i + (size_t)TOKENS * DDIM / 4];
    a.x += b.x; a.y += b.y; a.z += b.z; a.w += b.w;
    reinterpret_cast<float4*>(out)[i] = a;
}

// ---------------- launch ----------------
extern "C" void kernel_launch(void* const* d_in, const int* in_sizes, int n_in,
                              void* d_out, int out_size) {
    const float* x  = (const float*)d_in[0];
    const float* Wg = (const float*)d_in[1];
    const float* bg = (const float*)d_in[2];
    const float* We = (const float*)d_in[3];
    const float* be = (const float*)d_in[4];
    float* out = (float*)d_out;

    cudaFuncSetAttribute(moe_gemm_mma, cudaFuncAttributeMaxDynamicSharedMemorySize, SMEM_TOTAL);

    zero_cnt_kernel<<<1, 32>>>();
    prep_x_kernel<<<TOKENS * DDIM / 4 / 256, 256>>>(x);
    prep_we_kernel<<<dim3(DDIM / 32, DDIM / 32, NEXP), 256>>>(We);
    gate_kernel<<<TOKENS / 64, 256>>>(x, Wg, bg);

    dim3 grid(TOKENS / BM, DDIM / BN, NEXP);   // (64, 4, 8); empty row tiles early-exit
    moe_gemm_mma<<<grid, 256, SMEM_TOTAL>>>(be);

    combine_kernel<<<TOKENS * DDIM / 4 / 256, 256>>>(out);
}

// round 9
// speedup vs baseline: 4.2032x; 1.0762x over previous
#include <cuda_runtime.h>
#include <cuda_fp16.h>
#include <stdint.h>
#include <math.h>

#define TOKENS 8192
#define DDIM   1024
#define NEXP   8

#define BM 128
#define BN 128
#define BK 64
#define NKT (DDIM / BK)   // 16 k-chunks

// ---------------- scratch (allocation-free rule: __device__ globals) ----------------
__device__ int   g_cnt[NEXP];
__device__ int   g_tok[NEXP][TOKENS];    // packed: token*2 + slot
__device__ float g_wt [NEXP][TOKENS];
__device__ __half g_xh[TOKENS * DDIM];
__device__ __half g_Weh[NEXP * DDIM * DDIM];   // transposed: [e][n][k]
__device__ float g_scr[2 * TOKENS * DDIM];     // per-slot contributions

// ---------------- helpers ----------------
__device__ __forceinline__ uint32_t smem_u32(const void* p) {
    uint32_t a;
    asm("{ .reg .u64 t; cvta.to.shared.u64 t, %1; cvt.u32.u64 %0, t; }" : "=r"(a) : "l"(p));
    return a;
}

// SW128 swizzle for 128B rows (Swizzle<3,4,3>)
#define SWZ(o) ((o) ^ (((o) >> 3) & 0x70))

__device__ __forceinline__ void ldsm_x4(uint32_t* r, uint32_t addr) {
    asm volatile("ldmatrix.sync.aligned.m8n8.x4.shared.b16 {%0,%1,%2,%3}, [%4];"
                 : "=r"(r[0]), "=r"(r[1]), "=r"(r[2]), "=r"(r[3]) : "r"(addr));
}

__device__ __forceinline__ void mma_fp16(float* c, const uint32_t* a, uint32_t b0, uint32_t b1) {
    asm volatile("mma.sync.aligned.m16n8k16.row.col.f32.f16.f16.f32 "
                 "{%0,%1,%2,%3}, {%4,%5,%6,%7}, {%8,%9}, {%0,%1,%2,%3};"
                 : "+f"(c[0]), "+f"(c[1]), "+f"(c[2]), "+f"(c[3])
                 : "r"(a[0]), "r"(a[1]), "r"(a[2]), "r"(a[3]), "r"(b0), "r"(b1));
}

#define CP_ASYNC16(dst, src) \
    asm volatile("cp.async.cg.shared.global [%0], [%1], 16;" :: "r"(dst), "l"(src))
#define CP_COMMIT() asm volatile("cp.async.commit_group;" ::: "memory")
#define CP_WAIT(n)  asm volatile("cp.async.wait_group %0;" :: "n"(n) : "memory")

// ---------------- SMEM layout ----------------
// [0] ent_s 512 | [512] w_s 512 | [1024] 2 stages of (A 16K | B 16K)
#define SM_ENT   0
#define SM_W     512
#define SM_TILE  1024
#define A_BYTES  16384
#define STAGE_BYTES 32768
#define SMEM_TOTAL (SM_TILE + 2 * STAGE_BYTES)   // 66560

// ---------------- prep kernels ----------------
__global__ void zero_cnt_kernel() {
    if (threadIdx.x < NEXP) g_cnt[threadIdx.x] = 0;
}

__global__ void prep_x_kernel(const float* __restrict__ x) {
    const int i = blockIdx.x * 256 + threadIdx.x;     // one float4 each
    float4 v = reinterpret_cast<const float4*>(x)[i];
    __half2 h01 = __float22half2_rn(make_float2(v.x, v.y));
    __half2 h23 = __float22half2_rn(make_float2(v.z, v.w));
    reinterpret_cast<uint2*>(g_xh)[i] =
        make_uint2(*reinterpret_cast<uint32_t*>(&h01), *reinterpret_cast<uint32_t*>(&h23));
}

__global__ void prep_we_kernel(const float* __restrict__ We) {
    __shared__ float s[32][33];
    const int e  = blockIdx.z;
    const int n0 = blockIdx.x * 32;
    const int k0 = blockIdx.y * 32;
    const int tx = threadIdx.x & 31;
    const int ty = threadIdx.x >> 5;   // 0..7
    const float* src = We + ((size_t)e * DDIM + k0) * DDIM + n0;
#pragma unroll
    for (int i = 0; i < 4; i++)
        s[ty + i * 8][tx] = src[(size_t)(ty + i * 8) * DDIM + tx];
    __syncthreads();
#pragma unroll
    for (int i = 0; i < 4; i++) {
        const int nn = ty + i * 8;
        size_t o = ((size_t)e * DDIM + n0 + nn) * DDIM + k0 + tx;
        g_Weh[o] = __float2half_rn(s[tx][nn]);
    }
}

// warp handles 4 tokens; Wg slab held in registers, reused across tokens
__global__ __launch_bounds__(256)
void gate_kernel(const float* __restrict__ x,
                 const float* __restrict__ Wg,
                 const float* __restrict__ bg) {
    const int warp = threadIdx.x >> 5;
    const int lane = threadIdx.x & 31;
    const int t0 = (blockIdx.x * 8 + warp) * 4;

    float acc[4][NEXP];
#pragma unroll
    for (int tt = 0; tt < 4; tt++)
#pragma unroll
        for (int e = 0; e < NEXP; e++) acc[tt][e] = 0.f;

#pragma unroll
    for (int s = 0; s < 4; s++) {      // 4 slabs of 256 d
        float wg[8][NEXP];
#pragma unroll
        for (int i = 0; i < 8; i++) {
            const float4* wr = reinterpret_cast<const float4*>(
                Wg + (size_t)(s * 256 + i * 32 + lane) * NEXP);
            float4 w0 = wr[0], w1 = wr[1];
            wg[i][0] = w0.x; wg[i][1] = w0.y; wg[i][2] = w0.z; wg[i][3] = w0.w;
            wg[i][4] = w1.x; wg[i][5] = w1.y; wg[i][6] = w1.z; wg[i][7] = w1.w;
        }
#pragma unroll
        for (int tt = 0; tt < 4; tt++) {
            const float* xr = x + (size_t)(t0 + tt) * DDIM + s * 256 + lane;
#pragma unroll
            for (int i = 0; i < 8; i++) {
                float xv = xr[i * 32];
#pragma unroll
                for (int e = 0; e < NEXP; e++) acc[tt][e] += xv * wg[i][e];
            }
        }
    }

#pragma unroll
    for (int tt = 0; tt < 4; tt++) {
        float v[NEXP];
#pragma unroll
        for (int e = 0; e < NEXP; e++) {
            float r = acc[tt][e];
#pragma unroll
            for (int o = 16; o > 0; o >>= 1) r += __shfl_down_sync(0xffffffffu, r, o);
            v[e] = r;
        }
        if (lane == 0) {
            float v1 = -INFINITY, v2 = -INFINITY;
            int   i1 = 0, i2 = 0;
#pragma unroll
            for (int e = 0; e < NEXP; e++) {
                float s2 = v[e] + bg[e];
                if (s2 > v1)      { v2 = v1; i2 = i1; v1 = s2; i1 = e; }
                else if (s2 > v2) { v2 = s2; i2 = e; }
            }
            float l     = __expf(v2 - v1);
            float denom = 1.f + l;
            const int t = t0 + tt;
            int p1 = atomicAdd(&g_cnt[i1], 1);
            g_tok[i1][p1] = t * 2 + 0; g_wt[i1][p1] = 1.f / denom;
            int p2 = atomicAdd(&g_cnt[i2], 1);
            g_tok[i2][p2] = t * 2 + 1; g_wt[i2][p2] = l / denom;
        }
    }
}

// ---------------- HMMA grouped GEMM (fp16, 2-stage cp.async, 2 CTAs/SM) ----------------
__global__ __launch_bounds__(256, 2)
void moe_gemm_mma(const float* __restrict__ be) {
    const int e    = blockIdx.z;
    const int n    = g_cnt[e];
    const int row0 = blockIdx.x * BM;
    if (row0 >= n) return;
    const int col0   = blockIdx.y * BN;
    const int nvalid = min(BM, n - row0);

    extern __shared__ char smem[];
    int*   ent_s = (int*)(smem + SM_ENT);
    float* w_s   = (float*)(smem + SM_W);
    const uint32_t tiles_u = smem_u32(smem + SM_TILE);

    const int tid  = threadIdx.x;
    const int lane = tid & 31;
    const int wid  = tid >> 5;

    if (tid < BM) {
        int tk = 0; float w = 0.f;
        if (tid < nvalid) { tk = g_tok[e][row0 + tid]; w = g_wt[e][row0 + tid]; }
        ent_s[tid] = tk;
        w_s[tid]   = w;
    }
    __syncthreads();

    // ---- staging: thread covers granules (sh..sh+3) of A row sr and B row sr
    const int sr = tid >> 1;
    const int sh = (tid & 1) * 4;
    uint32_t og[4];
#pragma unroll
    for (int q = 0; q < 4; q++)
        og[q] = SWZ((uint32_t)(sr * 128 + (sh + q) * 16));

    const __half* aS = g_xh + (size_t)(ent_s[sr] >> 1) * DDIM + sh * 8;
    const __half* bS = g_Weh + ((size_t)e * DDIM + col0 + sr) * DDIM + sh * 8;

    // ---- compute assignment: warp tile 64x32
    const int m0  = (wid & 1) * 64;
    const int n0w = (wid >> 1) * 32;
    const int a_lrow = (lane & 7) + ((lane >> 3) & 1) * 8;
    const int a_lk   = ((lane >> 4) & 1) * 8;
    const int b_lrow = (lane & 7) + ((lane >> 4) & 1) * 8;
    const int b_lk   = ((lane >> 3) & 1) * 8;

    float acc[4][4][4];
#pragma unroll
    for (int i = 0; i < 4; i++)
#pragma unroll
        for (int j = 0; j < 4; j++)
#pragma unroll
            for (int q = 0; q < 4; q++) acc[i][j][q] = 0.f;

    // prologue: stage chunk 0
    {
#pragma unroll
        for (int q = 0; q < 4; q++) CP_ASYNC16(tiles_u + og[q], aS + q * 8);
#pragma unroll
        for (int q = 0; q < 4; q++) CP_ASYNC16(tiles_u + A_BYTES + og[q], bS + q * 8);
        CP_COMMIT();
    }

    for (int kt = 0; kt < NKT; kt++) {
        if (kt + 1 < NKT) {
            const uint32_t base = tiles_u + ((kt + 1) & 1) * STAGE_BYTES;
            const int kk = (kt + 1) * BK;
#pragma unroll
            for (int q = 0; q < 4; q++) CP_ASYNC16(base + og[q], aS + kk + q * 8);
#pragma unroll
            for (int q = 0; q < 4; q++) CP_ASYNC16(base + A_BYTES + og[q], bS + kk + q * 8);
            CP_COMMIT();
            CP_WAIT(1);            // chunk kt complete
        } else {
            CP_WAIT(0);
        }
        __syncthreads();

        const uint32_t AU = tiles_u + (kt & 1) * STAGE_BYTES;
        const uint32_t BU = AU + A_BYTES;
#pragma unroll
        for (int ks = 0; ks < 4; ks++) {
            uint32_t ah[4][4], bh[2][4];
#pragma unroll
            for (int mt = 0; mt < 4; mt++) {
                const uint32_t o = SWZ((uint32_t)((m0 + mt * 16 + a_lrow) * 128 +
                                                  (ks * 16 + a_lk) * 2));
                ldsm_x4(ah[mt], AU + o);
            }
#pragma unroll
            for (int np = 0; np < 2; np++) {
                const uint32_t o = SWZ((uint32_t)((n0w + np * 16 + b_lrow) * 128 +
                                                  (ks * 16 + b_lk) * 2));
                ldsm_x4(bh[np], BU + o);
            }
#pragma unroll
            for (int mt = 0; mt < 4; mt++)
#pragma unroll
                for (int nt = 0; nt < 4; nt++) {
                    const int bp = nt >> 1, bo = (nt & 1) * 2;
                    mma_fp16(acc[mt][nt], ah[mt], bh[bp][bo], bh[bp][bo + 1]);
                }
        }
        __syncthreads();   // chunk kt consumed (both warHalves) before restage
    }

    // ---- epilogue: scr[slot][token][col] = w * (acc + be[e][col]), plain stores
    const int gid = lane >> 2;
    const int tig = lane & 3;
    const float* beRow = be + (size_t)e * DDIM + col0;
#pragma unroll
    for (int mt = 0; mt < 4; mt++) {
        const int  rA = m0 + mt * 16 + gid;
        const int  rB = rA + 8;
        const bool vA = rA < nvalid;
        const bool vB = rB < nvalid;
        const int  entA = ent_s[rA];
        const int  entB = ent_s[rB];
        const float wA = w_s[rA];
        const float wB = w_s[rB];
        float* sA = g_scr + ((size_t)(entA >> 1) + (size_t)(entA & 1) * TOKENS) * DDIM + col0;
        float* sB = g_scr + ((size_t)(entB >> 1) + (size_t)(entB & 1) * TOKENS) * DDIM + col0;
#pragma unroll
        for (int nt = 0; nt < 4; nt++) {
            const int c = n0w + nt * 8 + tig * 2;
            const float2 bev = *reinterpret_cast<const float2*>(beRow + c);
            if (vA) {
                float2 v = make_float2(wA * (acc[mt][nt][0] + bev.x),
                                       wA * (acc[mt][nt][1] + bev.y));
                *reinterpret_cast<float2*>(sA + c) = v;
            }
            if (vB) {
                float2 v = make_float2(wB * (acc[mt][nt][2] + bev.x),
                                       wB * (acc[mt][nt][3] + bev.y));
                *reinterpret_cast<float2*>(sB + c) = v;
            }
        }
    }
}

__global__ void combine_kernel(float* __restrict__ out) {
    const size_t i = (size_t)blockIdx.x * 256 + threadIdx.x;   // float4 units
    const float4* s = reinterpret_cast<const float4*>(g_scr);
    float4 a = s[i];
    float4 b = s[i + (size_t)TOKENS * DDIM / 4];
    a.x += b.x; a.y += b.y; a.z += b.z; a.w += b.w;
    reinterpret_cast<float4*>(out)[i] = a;
}

// ---------------- launch ----------------
extern "C" void kernel_launch(void* const* d_in, const int* in_sizes, int n_in,
                              void* d_out, int out_size) {
    const float* x  = (const float*)d_in[0];
    const float* Wg = (const float*)d_in[1];
    const float* bg = (const float*)d_in[2];
    const float* We = (const float*)d_in[3];
    const float* be = (const float*)d_in[4];
    float* out = (float*)d_out;

    cudaFuncSetAttribute(moe_gemm_mma, cudaFuncAttributeMaxDynamicSharedMemorySize, SMEM_TOTAL);

    zero_cnt_kernel<<<1, 32>>>();
    prep_x_kernel<<<TOKENS * DDIM / 4 / 256, 256>>>(x);
    prep_we_kernel<<<dim3(DDIM / 32, DDIM / 32, NEXP), 256>>>(We);
    gate_kernel<<<TOKENS / 32, 256>>>(x, Wg, bg);

    dim3 grid(TOKENS / BM, DDIM / BN, NEXP);   // (64, 8, 8); empty row tiles early-exit
    moe_gemm_mma<<<grid, 256, SMEM_TOTAL>>>(be);

    combine_kernel<<<TOKENS * DDIM / 4 / 256, 256>>>(out);
}